// round 2
// baseline (speedup 1.0000x reference)
#include <cuda_runtime.h>
#include <cuda_bf16.h>
#include <math.h>

// Problem constants
#define BB 4
#define SS 1024
#define DD 1024
#define HH 16
#define DQ 64
#define DV 32
#define BS (BB*SS)          // 4096 rows
#define HDQ (HH*DQ)         // 1024
#define HDV (HH*DV)         // 512

typedef unsigned long long u64;

// packed f32x2 helpers (FFMA2 — 2x fp32 FMA throughput on sm_103a)
__device__ __forceinline__ u64 bc2(float v) {
    u64 r; asm("mov.b64 %0, {%1, %1};" : "=l"(r) : "f"(v)); return r;
}
__device__ __forceinline__ void ffma2(u64& d, u64 a, u64 b) {
    asm("fma.rn.f32x2 %0, %1, %2, %0;" : "+l"(d) : "l"(a), "l"(b));
}
__device__ __forceinline__ float2 up2(u64 v) {
    float2 f; asm("mov.b64 {%0, %1}, %2;" : "=f"(f.x), "=f"(f.y) : "l"(v)); return f;
}

// Scratch (device globals — allocation-free rule)
__device__ float g_Q[BS * HDQ];                    // [4096,1024]
__device__ float g_K[BS * HDQ];                    // [4096,1024]
__device__ float g_V[BS * HDV];                    // [4096,512]
__device__ float g_S[(size_t)BB * HH * SS * SS];   // [64,1024,1024] scores
__device__ float g_ctx[BS * DD];                   // [4096,1024] concat(fwd,bwd) ctx

// ---------------------------------------------------------------------------
// Generic SGEMM: C[M,N] = A[M,K] @ B[K,N] + bias[N]
// 128x128 tile, BK=8, 8x8 microtile (f32x2 packed), 256 threads.
// ---------------------------------------------------------------------------
__global__ __launch_bounds__(256) void sgemm_bias_kernel(
    const float* __restrict__ A, const float* __restrict__ B,
    const float* __restrict__ bias, float* __restrict__ C,
    int M, int N, int K)
{
    __shared__ float As[8][132];
    __shared__ float Bs[8][132];

    const int m0 = blockIdx.y * 128;
    const int n0 = blockIdx.x * 128;
    const int tid = threadIdx.x;
    const int tr = tid >> 4;      // 0..15
    const int tc = tid & 15;      // 0..15

    const int arow = tid >> 1;          // 0..127
    const int ac4  = (tid & 1) * 4;     // 0 or 4
    const int brow = tid >> 5;          // 0..7
    const int bc4  = (tid & 31) * 4;    // 0..124

    u64 acc2[8][4];
#pragma unroll
    for (int i = 0; i < 8; i++)
#pragma unroll
        for (int j = 0; j < 4; j++) acc2[i][j] = 0ull;

    for (int k0 = 0; k0 < K; k0 += 8) {
        float4 av = *(const float4*)(A + (size_t)(m0 + arow) * K + k0 + ac4);
        As[ac4 + 0][arow] = av.x;
        As[ac4 + 1][arow] = av.y;
        As[ac4 + 2][arow] = av.z;
        As[ac4 + 3][arow] = av.w;
        *(float4*)(&Bs[brow][bc4]) =
            *(const float4*)(B + (size_t)(k0 + brow) * N + n0 + bc4);
        __syncthreads();
#pragma unroll
        for (int kk = 0; kk < 8; kk++) {
            float4 a0 = *(const float4*)(&As[kk][tr * 8]);
            float4 a1 = *(const float4*)(&As[kk][tr * 8 + 4]);
            ulonglong2 b01 = *(const ulonglong2*)(&Bs[kk][tc * 8]);
            ulonglong2 b23 = *(const ulonglong2*)(&Bs[kk][tc * 8 + 4]);
            float ra[8] = {a0.x, a0.y, a0.z, a0.w, a1.x, a1.y, a1.z, a1.w};
#pragma unroll
            for (int i = 0; i < 8; i++) {
                u64 ai = bc2(ra[i]);
                ffma2(acc2[i][0], ai, b01.x);
                ffma2(acc2[i][1], ai, b01.y);
                ffma2(acc2[i][2], ai, b23.x);
                ffma2(acc2[i][3], ai, b23.y);
            }
        }
        __syncthreads();
    }

#pragma unroll
    for (int i = 0; i < 8; i++) {
        int row = m0 + tr * 8 + i;
        int col = n0 + tc * 8;
        float4 bv0 = *(const float4*)(bias + col);
        float4 bv1 = *(const float4*)(bias + col + 4);
        float2 c0 = up2(acc2[i][0]);
        float2 c1 = up2(acc2[i][1]);
        float2 c2 = up2(acc2[i][2]);
        float2 c3 = up2(acc2[i][3]);
        float4 o0 = make_float4(c0.x + bv0.x, c0.y + bv0.y, c1.x + bv0.z, c1.y + bv0.w);
        float4 o1 = make_float4(c2.x + bv1.x, c2.y + bv1.y, c3.x + bv1.z, c3.y + bv1.w);
        *(float4*)(C + (size_t)row * N + col) = o0;
        *(float4*)(C + (size_t)row * N + col + 4) = o1;
    }
}

// ---------------------------------------------------------------------------
// Scores: per (b,h)  Sc = Q_h [S,64] @ K_h^T [64,S] * 0.125
// 128x128 tile, BK=16 (K=64 total), 8x8 microtile (f32x2), 256 threads.
// ---------------------------------------------------------------------------
__global__ __launch_bounds__(256) void scores_kernel(float* __restrict__ Sc)
{
    const int bh = blockIdx.z;
    const int b = bh >> 4;
    const int h = bh & 15;
    const float* Ab = g_Q + (size_t)b * SS * HDQ + h * DQ;
    const float* Bb = g_K + (size_t)b * SS * HDQ + h * DQ;

    const int m0 = blockIdx.y * 128;
    const int n0 = blockIdx.x * 128;
    const int tid = threadIdx.x;
    const int tr = tid >> 4;
    const int tc = tid & 15;

    __shared__ float As[16][132];
    __shared__ float Bs[16][132];

    const int lrow = tid >> 2;         // 0..63
    const int lc4  = (tid & 3) * 4;    // 0,4,8,12

    u64 acc2[8][4];
#pragma unroll
    for (int i = 0; i < 8; i++)
#pragma unroll
        for (int j = 0; j < 4; j++) acc2[i][j] = 0ull;

    for (int k0 = 0; k0 < DQ; k0 += 16) {
#pragma unroll
        for (int p = 0; p < 2; p++) {
            int r = lrow + p * 64;
            float4 av = *(const float4*)(Ab + (size_t)(m0 + r) * HDQ + k0 + lc4);
            As[lc4 + 0][r] = av.x;
            As[lc4 + 1][r] = av.y;
            As[lc4 + 2][r] = av.z;
            As[lc4 + 3][r] = av.w;
            float4 bv = *(const float4*)(Bb + (size_t)(n0 + r) * HDQ + k0 + lc4);
            Bs[lc4 + 0][r] = bv.x;
            Bs[lc4 + 1][r] = bv.y;
            Bs[lc4 + 2][r] = bv.z;
            Bs[lc4 + 3][r] = bv.w;
        }
        __syncthreads();
#pragma unroll
        for (int kk = 0; kk < 16; kk++) {
            float4 a0 = *(const float4*)(&As[kk][tr * 8]);
            float4 a1 = *(const float4*)(&As[kk][tr * 8 + 4]);
            ulonglong2 b01 = *(const ulonglong2*)(&Bs[kk][tc * 8]);
            ulonglong2 b23 = *(const ulonglong2*)(&Bs[kk][tc * 8 + 4]);
            float ra[8] = {a0.x, a0.y, a0.z, a0.w, a1.x, a1.y, a1.z, a1.w};
#pragma unroll
            for (int i = 0; i < 8; i++) {
                u64 ai = bc2(ra[i]);
                ffma2(acc2[i][0], ai, b01.x);
                ffma2(acc2[i][1], ai, b01.y);
                ffma2(acc2[i][2], ai, b23.x);
                ffma2(acc2[i][3], ai, b23.y);
            }
        }
        __syncthreads();
    }

    float* Cb = Sc + (size_t)bh * SS * SS;
#pragma unroll
    for (int i = 0; i < 8; i++) {
        int row = m0 + tr * 8 + i;
        int col = n0 + tc * 8;
        float2 c0 = up2(acc2[i][0]);
        float2 c1 = up2(acc2[i][1]);
        float2 c2 = up2(acc2[i][2]);
        float2 c3 = up2(acc2[i][3]);
        float4 o0 = make_float4(c0.x * 0.125f, c0.y * 0.125f, c1.x * 0.125f, c1.y * 0.125f);
        float4 o1 = make_float4(c2.x * 0.125f, c2.y * 0.125f, c3.x * 0.125f, c3.y * 0.125f);
        *(float4*)(Cb + (size_t)row * SS + col) = o0;
        *(float4*)(Cb + (size_t)row * SS + col + 4) = o1;
    }
}

// ---------------------------------------------------------------------------
// Fused softmax + prob-write + PV.
// Per block: (bh, 32 q-rows). Scores tile in smem; per 128-key tile:
// compute probs -> write to attn (d_out) AND to smem prob buffers, load V
// tile, accumulate ctx[32][32] per direction. Probs never re-read from DRAM.
// 256 threads. Dyn smem: scores 32*1032 + probs 2*32*132 + V 128*36 floats.
// ---------------------------------------------------------------------------
#define SMROW 1032
#define OFF_P   (32 * SMROW)            // 33024
#define OFF_V   (OFF_P + 2 * 32 * 132)  // 41472
#define SM_FLOATS (OFF_V + 128 * 36)    // 46080 floats = 184320 B

__global__ __launch_bounds__(256) void softmax_pv_kernel(
    const float* __restrict__ Sc, float* __restrict__ attn)
{
    extern __shared__ float sm[];
    __shared__ float mF[32], iF[32], mB[32], iB[32];

    const int bh = blockIdx.y;
    const int b = bh >> 4;
    const int h = bh & 15;
    const int q0 = blockIdx.x * 32;
    const int tid = threadIdx.x;

    // Load scores tile [32][1024] into smem
    const float* src = Sc + (size_t)bh * SS * SS + (size_t)q0 * SS;
    for (int i = tid; i < 32 * SS; i += 256) {
        int r = i >> 10, k = i & 1023;
        sm[r * SMROW + k] = src[i];
    }
    __syncthreads();

    // Row stats: 8 threads per row
    {
        const int r = tid >> 3;
        const int t = tid & 7;
        const int q = q0 + r;
        const float* row = sm + r * SMROW;
        float mf = -1e30f, mb = -1e30f;
#pragma unroll 8
        for (int i = 0; i < 128; i++) {
            int k = t + (i << 3);
            float v = row[k];
            if (k <= q) mf = fmaxf(mf, v);
            if (k >= q) mb = fmaxf(mb, v);
        }
#pragma unroll
        for (int o = 4; o > 0; o >>= 1) {
            mf = fmaxf(mf, __shfl_xor_sync(0xffffffffu, mf, o));
            mb = fmaxf(mb, __shfl_xor_sync(0xffffffffu, mb, o));
        }
        float sf = 0.0f, sb = 0.0f;
#pragma unroll 8
        for (int i = 0; i < 128; i++) {
            int k = t + (i << 3);
            float v = row[k];
            if (k <= q) sf += __expf(v - mf);
            if (k >= q) sb += __expf(v - mb);
        }
#pragma unroll
        for (int o = 4; o > 0; o >>= 1) {
            sf += __shfl_xor_sync(0xffffffffu, sf, o);
            sb += __shfl_xor_sync(0xffffffffu, sb, o);
        }
        if (t == 0) {
            mF[r] = mf; iF[r] = 1.0f / sf;
            mB[r] = mb; iB[r] = 1.0f / sb;
        }
    }
    __syncthreads();

    // PV thread mapping: 128 threads per direction
    const int dir = tid >> 7;          // 0 fwd, 1 bwd
    const int t7 = tid & 127;
    const int ptr_r0 = (t7 >> 3) * 2;  // rows r0, r0+1
    const int ptc = t7 & 7;            // cols ptc*4..+3
    float* Pmine = sm + OFF_P + dir * 32 * 132;

    u64 acc[2][2];
    acc[0][0] = acc[0][1] = acc[1][0] = acc[1][1] = 0ull;

    // Prob-compute mapping: row = tid>>3, 16 keys starting at (tid&7)*16
    const int pr = tid >> 3;
    const int pk = (tid & 7) * 16;
    const int pq = q0 + pr;
    const float pmf = mF[pr], pif = iF[pr], pmb = mB[pr], pib = iB[pr];
    float* gdst = attn + (size_t)bh * SS * 2 * SS + (size_t)pq * 2048;
    float* Pf = sm + OFF_P;
    float* Pb2 = sm + OFF_P + 32 * 132;

    const float* Vb = g_V + (size_t)b * SS * HDV + h * DV;

    for (int k0 = 0; k0 < SS; k0 += 128) {
        // 1) probs: compute, write to gmem (both dirs) + smem buffers
#pragma unroll
        for (int j = 0; j < 16; j += 4) {
            float4 v = *(const float4*)(sm + pr * SMROW + k0 + pk + j);
            float vv[4] = {v.x, v.y, v.z, v.w};
            float pf[4], pb[4];
#pragma unroll
            for (int c = 0; c < 4; c++) {
                int k = k0 + pk + j + c;
                pf[c] = (k <= pq) ? __expf(vv[c] - pmf) * pif : 0.0f;
                pb[c] = (k >= pq) ? __expf(vv[c] - pmb) * pib : 0.0f;
            }
            float4 f4 = make_float4(pf[0], pf[1], pf[2], pf[3]);
            float4 b4 = make_float4(pb[0], pb[1], pb[2], pb[3]);
            *(float4*)(&Pf[pr * 132 + pk + j]) = f4;
            *(float4*)(&Pb2[pr * 132 + pk + j]) = b4;
            *(float4*)(gdst + k0 + pk + j) = f4;
            *(float4*)(gdst + 1024 + k0 + pk + j) = b4;
        }
        // 2) V tile [128][32] -> smem (row pad 36)
#pragma unroll
        for (int j = 0; j < 4; j++) {
            int idx = tid + j * 256;
            int vr = idx >> 3;
            int vc = (idx & 7) * 4;
            *(float4*)(sm + OFF_V + vr * 36 + vc) =
                *(const float4*)(Vb + (size_t)(k0 + vr) * HDV + vc);
        }
        __syncthreads();
        // 3) GEMM accumulate: ctx[2 rows][8 cols(4 packed x2)] += P @ Vtile
#pragma unroll 4
        for (int kk = 0; kk < 128; kk++) {
            u64 a0 = bc2(Pmine[ptr_r0 * 132 + kk]);
            u64 a1 = bc2(Pmine[(ptr_r0 + 1) * 132 + kk]);
            ulonglong2 bv = *(const ulonglong2*)(sm + OFF_V + kk * 36 + ptc * 4);
            ffma2(acc[0][0], a0, bv.x);
            ffma2(acc[0][1], a0, bv.y);
            ffma2(acc[1][0], a1, bv.x);
            ffma2(acc[1][1], a1, bv.y);
        }
        __syncthreads();
    }

    // Write ctx: rows q0+ptr_r0(+1), cols dir*512 + h*32 + ptc*4
#pragma unroll
    for (int i = 0; i < 2; i++) {
        int qr = q0 + ptr_r0 + i;
        float2 c0 = up2(acc[i][0]);
        float2 c1 = up2(acc[i][1]);
        float4 o = make_float4(c0.x, c0.y, c1.x, c1.y);
        *(float4*)(g_ctx + (size_t)((size_t)b * SS + qr) * DD
                   + dir * HDV + h * DV + ptc * 4) = o;
    }
}

// ---------------------------------------------------------------------------
// Launch
// ---------------------------------------------------------------------------
extern "C" void kernel_launch(void* const* d_in, const int* in_sizes, int n_in,
                              void* d_out, int out_size)
{
    const float* x  = (const float*)d_in[0];
    const float* Wq = (const float*)d_in[1];
    const float* bq = (const float*)d_in[2];
    const float* Wk = (const float*)d_in[3];
    const float* bk = (const float*)d_in[4];
    const float* Wv = (const float*)d_in[5];
    const float* bv = (const float*)d_in[6];
    const float* Wo = (const float*)d_in[7];
    const float* bo = (const float*)d_in[8];

    float* out  = (float*)d_out;                       // [B,S,D]
    float* attn = out + (size_t)BS * DD;               // [B,H,S,2S]

    float *pQ, *pK, *pV, *pS, *pC;
    cudaGetSymbolAddress((void**)&pQ, g_Q);
    cudaGetSymbolAddress((void**)&pK, g_K);
    cudaGetSymbolAddress((void**)&pV, g_V);
    cudaGetSymbolAddress((void**)&pS, g_S);
    cudaGetSymbolAddress((void**)&pC, g_ctx);

    // QKV projections
    sgemm_bias_kernel<<<dim3(HDQ / 128, BS / 128), 256>>>(x, Wq, bq, pQ, BS, HDQ, DD);
    sgemm_bias_kernel<<<dim3(HDQ / 128, BS / 128), 256>>>(x, Wk, bk, pK, BS, HDQ, DD);
    sgemm_bias_kernel<<<dim3(HDV / 128, BS / 128), 256>>>(x, Wv, bv, pV, BS, HDV, DD);

    // Scores
    scores_kernel<<<dim3(SS / 128, SS / 128, BB * HH), 256>>>(pS);

    // Fused softmax + prob write + PV
    const int smbytes = SM_FLOATS * 4;
    cudaFuncSetAttribute(softmax_pv_kernel,
                         cudaFuncAttributeMaxDynamicSharedMemorySize, smbytes);
    softmax_pv_kernel<<<dim3(SS / 32, BB * HH), 256, smbytes>>>(pS, attn);

    // Output projection
    sgemm_bias_kernel<<<dim3(DD / 128, BS / 128), 256>>>(pC, Wo, bo, out, BS, DD, DD);
}

// round 3
// speedup vs baseline: 1.1633x; 1.1633x over previous
#include <cuda_runtime.h>
#include <cuda_bf16.h>
#include <math.h>

#define BB 4
#define SS 1024
#define DD 1024
#define HH 16
#define DQ 64
#define DV 32
#define BS (BB*SS)          // 4096
#define HDQ (HH*DQ)         // 1024
#define HDV (HH*DV)         // 512

// ---------------- scratch (device globals; allocation-free rule) ------------
__device__ unsigned g_xh[BS * DD],  g_xl[BS * DD];        // split input
__device__ unsigned g_Wqh[DD * HDQ], g_Wql[DD * HDQ];
__device__ unsigned g_Wkh[DD * HDQ], g_Wkl[DD * HDQ];
__device__ unsigned g_Wvh[DD * HDV], g_Wvl[DD * HDV];
__device__ unsigned g_Woh[DD * DD],  g_Wol[DD * DD];
__device__ unsigned g_Qh[BS * HDQ],  g_Ql[BS * HDQ];
__device__ unsigned g_Kh[BS * HDQ],  g_Kl[BS * HDQ];
__device__ unsigned g_Vh[BS * HDV],  g_Vl[BS * HDV];
__device__ unsigned g_Ch[BS * DD],   g_Cl[BS * DD];       // split ctx
__device__ float    g_S[(size_t)BB * HH * SS * SS];       // scores fp32

// ---------------- helpers ---------------------------------------------------
__device__ __forceinline__ void split_tf32(float f, unsigned& h, unsigned& l) {
    unsigned th; asm("cvt.rna.tf32.f32 %0, %1;" : "=r"(th) : "f"(f));
    float fl = f - __uint_as_float(th);
    unsigned tl; asm("cvt.rna.tf32.f32 %0, %1;" : "=r"(tl) : "f"(fl));
    h = th; l = tl;
}

__device__ __forceinline__ void mma8(float* c, const unsigned* a, const unsigned* b) {
    asm("mma.sync.aligned.m16n8k8.row.col.f32.tf32.tf32.f32 "
        "{%0,%1,%2,%3}, {%4,%5,%6,%7}, {%8,%9}, {%0,%1,%2,%3};"
        : "+f"(c[0]), "+f"(c[1]), "+f"(c[2]), "+f"(c[3])
        : "r"(a[0]), "r"(a[1]), "r"(a[2]), "r"(a[3]), "r"(b[0]), "r"(b[1]));
}

// ---------------- split pre-pass --------------------------------------------
__global__ __launch_bounds__(256) void split_kernel(
    const float* __restrict__ in, unsigned* __restrict__ hi,
    unsigned* __restrict__ lo, int n4)
{
    for (int i = blockIdx.x * 256 + threadIdx.x; i < n4; i += gridDim.x * 256) {
        float4 v = ((const float4*)in)[i];
        uint4 h, l;
        split_tf32(v.x, h.x, l.x);
        split_tf32(v.y, h.y, l.y);
        split_tf32(v.z, h.z, l.z);
        split_tf32(v.w, h.w, l.w);
        ((uint4*)hi)[i] = h;
        ((uint4*)lo)[i] = l;
    }
}

// ---------------- NN GEMM: C[M,N] = A@B + bias  (A,B pre-split tf32) --------
// 128x128 tile, BK=32, 8 warps (2x4), warp tile 64x32, m16n8k8 x 3 (split).
#define ANR 36
#define BNR 136
#define NN_SMEM ((128*ANR*2 + 32*BNR*2) * 4)

__global__ __launch_bounds__(256) void gemm_nn_tf32(
    const unsigned* __restrict__ Ah, const unsigned* __restrict__ Al,
    const unsigned* __restrict__ Bh, const unsigned* __restrict__ Bl,
    const float* __restrict__ bias,
    float* __restrict__ outF, unsigned* __restrict__ outH,
    unsigned* __restrict__ outL, int M, int N, int K)
{
    extern __shared__ unsigned sm_[];
    unsigned* Ash = sm_;
    unsigned* Asl = Ash + 128 * ANR;
    unsigned* Bsh = Asl + 128 * ANR;
    unsigned* Bsl = Bsh + 32 * BNR;

    const int m0 = blockIdx.y * 128, n0 = blockIdx.x * 128;
    const int tid = threadIdx.x, lane = tid & 31, wid = tid >> 5;
    const int wm0 = (wid >> 2) * 64, wn0 = (wid & 3) * 32;
    const int lr = lane >> 2, lc = lane & 3;

    float acc[4][4][4];
#pragma unroll
    for (int i = 0; i < 4; i++)
#pragma unroll
        for (int j = 0; j < 4; j++)
#pragma unroll
            for (int k = 0; k < 4; k++) acc[i][j][k] = 0.0f;

    for (int k0 = 0; k0 < K; k0 += 32) {
#pragma unroll
        for (int j = 0; j < 4; j++) {
            int e = tid + j * 256;
            int r = e >> 3, c4 = (e & 7) * 4;
            size_t ga = (size_t)(m0 + r) * K + k0 + c4;
            *(uint4*)(Ash + r * ANR + c4) = *(const uint4*)(Ah + ga);
            *(uint4*)(Asl + r * ANR + c4) = *(const uint4*)(Al + ga);
        }
#pragma unroll
        for (int j = 0; j < 4; j++) {
            int e = tid + j * 256;
            int kk = e >> 5, n4 = (e & 31) * 4;
            size_t gb = (size_t)(k0 + kk) * N + n0 + n4;
            *(uint4*)(Bsh + kk * BNR + n4) = *(const uint4*)(Bh + gb);
            *(uint4*)(Bsl + kk * BNR + n4) = *(const uint4*)(Bl + gb);
        }
        __syncthreads();
#pragma unroll
        for (int ks = 0; ks < 32; ks += 8) {
            unsigned ah[4][4], al[4][4], bh[4][2], bl[4][2];
#pragma unroll
            for (int mt = 0; mt < 4; mt++) {
                int base = (wm0 + mt * 16 + lr) * ANR + ks + lc;
                ah[mt][0] = Ash[base];
                ah[mt][1] = Ash[base + 8 * ANR];
                ah[mt][2] = Ash[base + 4];
                ah[mt][3] = Ash[base + 8 * ANR + 4];
                al[mt][0] = Asl[base];
                al[mt][1] = Asl[base + 8 * ANR];
                al[mt][2] = Asl[base + 4];
                al[mt][3] = Asl[base + 8 * ANR + 4];
            }
#pragma unroll
            for (int nt = 0; nt < 4; nt++) {
                int b0 = (ks + lc) * BNR + wn0 + nt * 8 + lr;
                bh[nt][0] = Bsh[b0];
                bh[nt][1] = Bsh[b0 + 4 * BNR];
                bl[nt][0] = Bsl[b0];
                bl[nt][1] = Bsl[b0 + 4 * BNR];
            }
#pragma unroll
            for (int mt = 0; mt < 4; mt++)
#pragma unroll
                for (int nt = 0; nt < 4; nt++) {
                    mma8(acc[mt][nt], ah[mt], bh[nt]);
                    mma8(acc[mt][nt], ah[mt], bl[nt]);
                    mma8(acc[mt][nt], al[mt], bh[nt]);
                }
        }
        __syncthreads();
    }

#pragma unroll
    for (int mt = 0; mt < 4; mt++)
#pragma unroll
        for (int nt = 0; nt < 4; nt++) {
            int r = m0 + wm0 + mt * 16 + lr;
            int c = n0 + wn0 + nt * 8 + 2 * lc;
            float b0 = bias[c], b1 = bias[c + 1];
            float v00 = acc[mt][nt][0] + b0, v01 = acc[mt][nt][1] + b1;
            float v10 = acc[mt][nt][2] + b0, v11 = acc[mt][nt][3] + b1;
            if (outF) {
                *(float2*)(outF + (size_t)r * N + c) = make_float2(v00, v01);
                *(float2*)(outF + (size_t)(r + 8) * N + c) = make_float2(v10, v11);
            } else {
                uint2 h0, l0, h1, l1;
                split_tf32(v00, h0.x, l0.x); split_tf32(v01, h0.y, l0.y);
                split_tf32(v10, h1.x, l1.x); split_tf32(v11, h1.y, l1.y);
                *(uint2*)(outH + (size_t)r * N + c) = h0;
                *(uint2*)(outL + (size_t)r * N + c) = l0;
                *(uint2*)(outH + (size_t)(r + 8) * N + c) = h1;
                *(uint2*)(outL + (size_t)(r + 8) * N + c) = l1;
            }
        }
}

// ---------------- scores: S = Q @ K^T * 0.125 (NT, split tf32) --------------
#define SC_SMEM (128*ANR*4*4)

__global__ __launch_bounds__(256) void scores_tf32_kernel(float* __restrict__ Sc)
{
    extern __shared__ unsigned sm_[];
    unsigned* Ash = sm_;
    unsigned* Asl = Ash + 128 * ANR;
    unsigned* Bsh = Asl + 128 * ANR;
    unsigned* Bsl = Bsh + 128 * ANR;

    const int bh = blockIdx.z;
    const int b = bh >> 4, h = bh & 15;
    const int m0 = blockIdx.y * 128, n0 = blockIdx.x * 128;
    const int tid = threadIdx.x, lane = tid & 31, wid = tid >> 5;
    const int wm0 = (wid >> 2) * 64, wn0 = (wid & 3) * 32;
    const int lr = lane >> 2, lc = lane & 3;

    const size_t qbase = (size_t)b * SS * HDQ + h * DQ;

    float acc[4][4][4];
#pragma unroll
    for (int i = 0; i < 4; i++)
#pragma unroll
        for (int j = 0; j < 4; j++)
#pragma unroll
            for (int k = 0; k < 4; k++) acc[i][j][k] = 0.0f;

    for (int k0 = 0; k0 < DQ; k0 += 32) {
#pragma unroll
        for (int j = 0; j < 4; j++) {
            int e = tid + j * 256;
            int r = e >> 3, c4 = (e & 7) * 4;
            size_t ga = qbase + (size_t)(m0 + r) * HDQ + k0 + c4;
            *(uint4*)(Ash + r * ANR + c4) = *(const uint4*)(g_Qh + ga);
            *(uint4*)(Asl + r * ANR + c4) = *(const uint4*)(g_Ql + ga);
            size_t gb = qbase + (size_t)(n0 + r) * HDQ + k0 + c4;
            *(uint4*)(Bsh + r * ANR + c4) = *(const uint4*)(g_Kh + gb);
            *(uint4*)(Bsl + r * ANR + c4) = *(const uint4*)(g_Kl + gb);
        }
        __syncthreads();
#pragma unroll
        for (int ks = 0; ks < 32; ks += 8) {
            unsigned ah[4][4], al[4][4], bh2[4][2], bl2[4][2];
#pragma unroll
            for (int mt = 0; mt < 4; mt++) {
                int base = (wm0 + mt * 16 + lr) * ANR + ks + lc;
                ah[mt][0] = Ash[base];
                ah[mt][1] = Ash[base + 8 * ANR];
                ah[mt][2] = Ash[base + 4];
                ah[mt][3] = Ash[base + 8 * ANR + 4];
                al[mt][0] = Asl[base];
                al[mt][1] = Asl[base + 8 * ANR];
                al[mt][2] = Asl[base + 4];
                al[mt][3] = Asl[base + 8 * ANR + 4];
            }
#pragma unroll
            for (int nt = 0; nt < 4; nt++) {
                int base = (wn0 + nt * 8 + lr) * ANR + ks + lc;
                bh2[nt][0] = Bsh[base];
                bh2[nt][1] = Bsh[base + 4];
                bl2[nt][0] = Bsl[base];
                bl2[nt][1] = Bsl[base + 4];
            }
#pragma unroll
            for (int mt = 0; mt < 4; mt++)
#pragma unroll
                for (int nt = 0; nt < 4; nt++) {
                    mma8(acc[mt][nt], ah[mt], bh2[nt]);
                    mma8(acc[mt][nt], ah[mt], bl2[nt]);
                    mma8(acc[mt][nt], al[mt], bh2[nt]);
                }
        }
        __syncthreads();
    }

    float* Cb = Sc + (size_t)bh * SS * SS;
#pragma unroll
    for (int mt = 0; mt < 4; mt++)
#pragma unroll
        for (int nt = 0; nt < 4; nt++) {
            int r = m0 + wm0 + mt * 16 + lr;
            int c = n0 + wn0 + nt * 8 + 2 * lc;
            *(float2*)(Cb + (size_t)r * SS + c) =
                make_float2(acc[mt][nt][0] * 0.125f, acc[mt][nt][1] * 0.125f);
            *(float2*)(Cb + (size_t)(r + 8) * SS + c) =
                make_float2(acc[mt][nt][2] * 0.125f, acc[mt][nt][3] * 0.125f);
        }
}

// ---------------- softmax (R1 version): writes probs to attn ----------------
#define SMROW 1032
__global__ __launch_bounds__(256) void softmax_kernel(
    const float* __restrict__ Sc, float* __restrict__ attn)
{
    extern __shared__ float ssc[];
    __shared__ float mF[32], iF[32], mB[32], iB[32];

    const int bh = blockIdx.y;
    const int q0 = blockIdx.x * 32;
    const int tid = threadIdx.x;

    const float* src = Sc + (size_t)bh * SS * SS + (size_t)q0 * SS;
    for (int i = tid; i < 32 * SS; i += 256) {
        int r = i >> 10, k = i & 1023;
        ssc[r * SMROW + k] = src[i];
    }
    __syncthreads();

    const int r = tid >> 3;
    const int t = tid & 7;
    const int q = q0 + r;
    const float* row = ssc + r * SMROW;

    float mf = -1e30f, mb = -1e30f;
#pragma unroll 8
    for (int i = 0; i < 128; i++) {
        int k = t + (i << 3);
        float v = row[k];
        if (k <= q) mf = fmaxf(mf, v);
        if (k >= q) mb = fmaxf(mb, v);
    }
#pragma unroll
    for (int o = 4; o > 0; o >>= 1) {
        mf = fmaxf(mf, __shfl_xor_sync(0xffffffffu, mf, o));
        mb = fmaxf(mb, __shfl_xor_sync(0xffffffffu, mb, o));
    }
    float sf = 0.0f, sb = 0.0f;
#pragma unroll 8
    for (int i = 0; i < 128; i++) {
        int k = t + (i << 3);
        float v = row[k];
        if (k <= q) sf += __expf(v - mf);
        if (k >= q) sb += __expf(v - mb);
    }
#pragma unroll
    for (int o = 4; o > 0; o >>= 1) {
        sf += __shfl_xor_sync(0xffffffffu, sf, o);
        sb += __shfl_xor_sync(0xffffffffu, sb, o);
    }
    if (t == 0) {
        mF[r] = mf; iF[r] = 1.0f / sf;
        mB[r] = mb; iB[r] = 1.0f / sb;
    }
    __syncthreads();

    float* dst = attn + (size_t)bh * SS * 2 * SS + (size_t)q0 * 2 * SS;
    for (int i = tid; i < 32 * SS; i += 256) {
        int rr = i >> 10, k = i & 1023;
        int qq = q0 + rr;
        float v = ssc[rr * SMROW + k];
        float pf = (k <= qq) ? __expf(v - mF[rr]) * iF[rr] : 0.0f;
        float pb = (k >= qq) ? __expf(v - mB[rr]) * iB[rr] : 0.0f;
        dst[(size_t)rr * 2048 + k] = pf;
        dst[(size_t)rr * 2048 + 1024 + k] = pb;
    }
}

// ---------------- PV: ctx = P @ V  (P split on-the-fly, V pre-split) --------
#define VNR 40
#define PV_SMEM ((128*ANR*2 + 32*VNR*2) * 4)

__global__ __launch_bounds__(256) void pv_tf32_kernel(const float* __restrict__ attn)
{
    extern __shared__ unsigned sm_[];
    unsigned* Psh = sm_;
    unsigned* Psl = Psh + 128 * ANR;
    unsigned* Vsh = Psl + 128 * ANR;
    unsigned* Vsl = Vsh + 32 * VNR;

    const int bh = blockIdx.z;
    const int dir = blockIdx.y;
    const int q0 = blockIdx.x * 128;
    const int b = bh >> 4, h = bh & 15;
    const int tid = threadIdx.x, lane = tid & 31, wid = tid >> 5;
    const int lr = lane >> 2, lc = lane & 3;

    const float* Pb = attn + (size_t)bh * SS * 2 * SS + dir * SS;
    const size_t vbase = (size_t)b * SS * HDV + h * DV;

    float acc[4][4];
#pragma unroll
    for (int i = 0; i < 4; i++)
#pragma unroll
        for (int j = 0; j < 4; j++) acc[i][j] = 0.0f;

    for (int k0 = 0; k0 < SS; k0 += 32) {
#pragma unroll
        for (int j = 0; j < 4; j++) {
            int e = tid + j * 256;
            int r = e >> 3, c4 = (e & 7) * 4;
            float4 p = *(const float4*)(Pb + (size_t)(q0 + r) * 2048 + k0 + c4);
            uint4 hh, ll;
            split_tf32(p.x, hh.x, ll.x);
            split_tf32(p.y, hh.y, ll.y);
            split_tf32(p.z, hh.z, ll.z);
            split_tf32(p.w, hh.w, ll.w);
            *(uint4*)(Psh + r * ANR + c4) = hh;
            *(uint4*)(Psl + r * ANR + c4) = ll;
        }
        {
            int k = tid >> 3, d4 = (tid & 7) * 4;
            size_t gv = vbase + (size_t)(k0 + k) * HDV + d4;
            *(uint4*)(Vsh + k * VNR + d4) = *(const uint4*)(g_Vh + gv);
            *(uint4*)(Vsl + k * VNR + d4) = *(const uint4*)(g_Vl + gv);
        }
        __syncthreads();
#pragma unroll
        for (int ks = 0; ks < 32; ks += 8) {
            unsigned ah[4], al[4];
            int base = (wid * 16 + lr) * ANR + ks + lc;
            ah[0] = Psh[base];
            ah[1] = Psh[base + 8 * ANR];
            ah[2] = Psh[base + 4];
            ah[3] = Psh[base + 8 * ANR + 4];
            al[0] = Psl[base];
            al[1] = Psl[base + 8 * ANR];
            al[2] = Psl[base + 4];
            al[3] = Psl[base + 8 * ANR + 4];
#pragma unroll
            for (int nt = 0; nt < 4; nt++) {
                unsigned bh2[2], bl2[2];
                int b0 = (ks + lc) * VNR + nt * 8 + lr;
                bh2[0] = Vsh[b0];
                bh2[1] = Vsh[b0 + 4 * VNR];
                bl2[0] = Vsl[b0];
                bl2[1] = Vsl[b0 + 4 * VNR];
                mma8(acc[nt], ah, bh2);
                mma8(acc[nt], ah, bl2);
                mma8(acc[nt], al, bh2);
            }
        }
        __syncthreads();
    }

#pragma unroll
    for (int nt = 0; nt < 4; nt++) {
        int r = q0 + wid * 16 + lr;
        int c = dir * HDV + h * DV + nt * 8 + 2 * lc;
        uint2 h0, l0, h1, l1;
        split_tf32(acc[nt][0], h0.x, l0.x);
        split_tf32(acc[nt][1], h0.y, l0.y);
        split_tf32(acc[nt][2], h1.x, l1.x);
        split_tf32(acc[nt][3], h1.y, l1.y);
        *(uint2*)(g_Ch + (size_t)((size_t)b * SS + r) * DD + c) = h0;
        *(uint2*)(g_Cl + (size_t)((size_t)b * SS + r) * DD + c) = l0;
        *(uint2*)(g_Ch + (size_t)((size_t)b * SS + r + 8) * DD + c) = h1;
        *(uint2*)(g_Cl + (size_t)((size_t)b * SS + r + 8) * DD + c) = l1;
    }
}

// ---------------- launch -----------------------------------------------------
extern "C" void kernel_launch(void* const* d_in, const int* in_sizes, int n_in,
                              void* d_out, int out_size)
{
    const float* x  = (const float*)d_in[0];
    const float* Wq = (const float*)d_in[1];
    const float* bq = (const float*)d_in[2];
    const float* Wk = (const float*)d_in[3];
    const float* bk = (const float*)d_in[4];
    const float* Wv = (const float*)d_in[5];
    const float* bv = (const float*)d_in[6];
    const float* Wo = (const float*)d_in[7];
    const float* bo = (const float*)d_in[8];

    float* out  = (float*)d_out;
    float* attn = out + (size_t)BS * DD;

    unsigned *xh, *xl, *Wqh, *Wql, *Wkh, *Wkl, *Wvh, *Wvl, *Woh, *Wol;
    unsigned *Qh, *Ql, *Kh, *Kl, *Vh, *Vl, *Ch, *Cl;
    float* pS;
    cudaGetSymbolAddress((void**)&xh, g_xh);   cudaGetSymbolAddress((void**)&xl, g_xl);
    cudaGetSymbolAddress((void**)&Wqh, g_Wqh); cudaGetSymbolAddress((void**)&Wql, g_Wql);
    cudaGetSymbolAddress((void**)&Wkh, g_Wkh); cudaGetSymbolAddress((void**)&Wkl, g_Wkl);
    cudaGetSymbolAddress((void**)&Wvh, g_Wvh); cudaGetSymbolAddress((void**)&Wvl, g_Wvl);
    cudaGetSymbolAddress((void**)&Woh, g_Woh); cudaGetSymbolAddress((void**)&Wol, g_Wol);
    cudaGetSymbolAddress((void**)&Qh, g_Qh);   cudaGetSymbolAddress((void**)&Ql, g_Ql);
    cudaGetSymbolAddress((void**)&Kh, g_Kh);   cudaGetSymbolAddress((void**)&Kl, g_Kl);
    cudaGetSymbolAddress((void**)&Vh, g_Vh);   cudaGetSymbolAddress((void**)&Vl, g_Vl);
    cudaGetSymbolAddress((void**)&Ch, g_Ch);   cudaGetSymbolAddress((void**)&Cl, g_Cl);
    cudaGetSymbolAddress((void**)&pS, g_S);

    cudaFuncSetAttribute(gemm_nn_tf32,
                         cudaFuncAttributeMaxDynamicSharedMemorySize, NN_SMEM);
    cudaFuncSetAttribute(scores_tf32_kernel,
                         cudaFuncAttributeMaxDynamicSharedMemorySize, SC_SMEM);
    cudaFuncSetAttribute(pv_tf32_kernel,
                         cudaFuncAttributeMaxDynamicSharedMemorySize, PV_SMEM);
    cudaFuncSetAttribute(softmax_kernel,
                         cudaFuncAttributeMaxDynamicSharedMemorySize, 32 * SMROW * 4);

    // pre-split inputs + weights
    split_kernel<<<512, 256>>>(x,  xh,  xl,  BS * DD / 4);
    split_kernel<<<256, 256>>>(Wq, Wqh, Wql, DD * HDQ / 4);
    split_kernel<<<256, 256>>>(Wk, Wkh, Wkl, DD * HDQ / 4);
    split_kernel<<<256, 256>>>(Wv, Wvh, Wvl, DD * HDV / 4);
    split_kernel<<<256, 256>>>(Wo, Woh, Wol, DD * DD / 4);

    // projections (write split outputs)
    gemm_nn_tf32<<<dim3(HDQ / 128, BS / 128), 256, NN_SMEM>>>(
        xh, xl, Wqh, Wql, bq, nullptr, Qh, Ql, BS, HDQ, DD);
    gemm_nn_tf32<<<dim3(HDQ / 128, BS / 128), 256, NN_SMEM>>>(
        xh, xl, Wkh, Wkl, bk, nullptr, Kh, Kl, BS, HDQ, DD);
    gemm_nn_tf32<<<dim3(HDV / 128, BS / 128), 256, NN_SMEM>>>(
        xh, xl, Wvh, Wvl, bv, nullptr, Vh, Vl, BS, HDV, DD);

    // scores
    scores_tf32_kernel<<<dim3(SS / 128, SS / 128, BB * HH), 256, SC_SMEM>>>(pS);

    // softmax + prob write
    softmax_kernel<<<dim3(SS / 32, BB * HH), 256, 32 * SMROW * 4>>>(pS, attn);

    // PV
    pv_tf32_kernel<<<dim3(SS / 128, 2, BB * HH), 256, PV_SMEM>>>(attn);

    // output projection (fp32 + bias)
    gemm_nn_tf32<<<dim3(DD / 128, BS / 128), 256, NN_SMEM>>>(
        Ch, Cl, Woh, Wol, bo, out, nullptr, nullptr, BS, DD, DD);
}

// round 6
// speedup vs baseline: 1.5638x; 1.3443x over previous
#include <cuda_runtime.h>
#include <cuda_bf16.h>
#include <math.h>
#include <stdint.h>

#define BB 4
#define SS 1024
#define DD 1024
#define HH 16
#define DQ 64
#define DV 32
#define BS (BB*SS)          // 4096
#define HDQ (HH*DQ)         // 1024
#define HDV (HH*DV)         // 512

typedef __nv_bfloat16 bf16;

// ---------------- scratch (device globals; allocation-free rule) ------------
__device__ bf16 g_xh[BS * DD],  g_xl[BS * DD];            // split input
__device__ bf16 g_WqTh[HDQ * DD], g_WqTl[HDQ * DD];       // W^T split [N][K]
__device__ bf16 g_WkTh[HDQ * DD], g_WkTl[HDQ * DD];
__device__ bf16 g_WvTh[HDV * DD], g_WvTl[HDV * DD];
__device__ bf16 g_WoTh[DD * DD],  g_WoTl[DD * DD];
__device__ bf16 g_Qh[BS * HDQ],  g_Ql[BS * HDQ];          // [token][d]
__device__ bf16 g_Kh[BS * HDQ],  g_Kl[BS * HDQ];          // [token][d]
__device__ bf16 g_VTh[HDV * BS], g_VTl[HDV * BS];         // V^T [d][token]
__device__ bf16 g_Ch[BS * DD],   g_Cl[BS * DD];           // ctx split
__device__ float g_S[(size_t)BB * HH * SS * SS];          // scores fp32

// ---------------- helpers ---------------------------------------------------
__device__ __forceinline__ void split_bf(float f, bf16& h, bf16& l) {
    h = __float2bfloat16(f);
    l = __float2bfloat16(f - __bfloat162float(h));
}
__device__ __forceinline__ uint32_t pk2(bf16 a, bf16 b) {
    return (uint32_t)__bfloat16_as_ushort(a) |
           ((uint32_t)__bfloat16_as_ushort(b) << 16);
}
__device__ __forceinline__ void mma16(float* c, const uint32_t* a, const uint32_t* b) {
    asm("mma.sync.aligned.m16n8k16.row.col.f32.bf16.bf16.f32 "
        "{%0,%1,%2,%3}, {%4,%5,%6,%7}, {%8,%9}, {%0,%1,%2,%3};"
        : "+f"(c[0]), "+f"(c[1]), "+f"(c[2]), "+f"(c[3])
        : "r"(a[0]), "r"(a[1]), "r"(a[2]), "r"(a[3]), "r"(b[0]), "r"(b[1]));
}

// ---------------- split pre-passes ------------------------------------------
__global__ __launch_bounds__(256) void split_x_kernel(
    const float* __restrict__ in, bf16* __restrict__ hi,
    bf16* __restrict__ lo, int n4)
{
    for (int i = blockIdx.x * 256 + threadIdx.x; i < n4; i += gridDim.x * 256) {
        float4 v = ((const float4*)in)[i];
        bf16 h0, l0, h1, l1, h2, l2, h3, l3;
        split_bf(v.x, h0, l0); split_bf(v.y, h1, l1);
        split_bf(v.z, h2, l2); split_bf(v.w, h3, l3);
        ((uint2*)hi)[i] = make_uint2(pk2(h0, h1), pk2(h2, h3));
        ((uint2*)lo)[i] = make_uint2(pk2(l0, l1), pk2(l2, l3));
    }
}

// Transpose + split: W [K][N] fp32 -> T [N][K] bf16 hi/lo
__global__ void splitT_kernel(const float* __restrict__ W,
                              bf16* __restrict__ Th, bf16* __restrict__ Tl,
                              int K, int N)
{
    __shared__ float t[32][33];
    const int n0 = blockIdx.x * 32, k0 = blockIdx.y * 32;
    const int tx = threadIdx.x, ty = threadIdx.y;
#pragma unroll
    for (int i = 0; i < 32; i += 8)
        t[ty + i][tx] = W[(size_t)(k0 + ty + i) * N + n0 + tx];
    __syncthreads();
#pragma unroll
    for (int i = 0; i < 32; i += 8) {
        float v = t[tx][ty + i];
        bf16 h, l; split_bf(v, h, l);
        Th[(size_t)(n0 + ty + i) * K + k0 + tx] = h;
        Tl[(size_t)(n0 + ty + i) * K + k0 + tx] = l;
    }
}

// ---------------- unified bf16-split GEMM (synchronous loads) ---------------
// C[M,N] = (A @ Bt^T) * scale + bias   (A row-major [M][K], Bt row-major [N][K])
// OUT=0: fp32 C. OUT=1: split bf16 row-major. OUT=2: split bf16 transposed.
// 128x128 tile, BK=32, 8 warps (2x4 warp grid), warp tile 64x32.
#define PITCH 40   // bf16 elements per smem row (32 data + 8 pad)

template<int OUT>
__global__ __launch_bounds__(256) void gemm_bf16(
    const bf16* __restrict__ Ah, const bf16* __restrict__ Al, int lda,
    const bf16* __restrict__ Bth, const bf16* __restrict__ Btl, int ldb,
    const float* __restrict__ bias, float scale,
    float* __restrict__ outF, bf16* __restrict__ outH, bf16* __restrict__ outL,
    int ldc, int M, int N, int K, size_t zb, size_t zh, size_t cB)
{
    __shared__ __align__(16) bf16 Ash[128 * PITCH];
    __shared__ __align__(16) bf16 Asl[128 * PITCH];
    __shared__ __align__(16) bf16 Bsh[128 * PITCH];
    __shared__ __align__(16) bf16 Bsl[128 * PITCH];

    const int z = blockIdx.z;
    const size_t offAB = (size_t)(z >> 4) * zb + (size_t)(z & 15) * zh;

    const int m0 = blockIdx.y * 128, n0 = blockIdx.x * 128;
    const int tid = threadIdx.x, lane = tid & 31, wid = tid >> 5;
    const int wm0 = (wid >> 2) * 64, wn0 = (wid & 3) * 32;
    const int lr = lane >> 2, lc = lane & 3;

    float acc[4][4][4];
#pragma unroll
    for (int i = 0; i < 4; i++)
#pragma unroll
        for (int j = 0; j < 4; j++)
#pragma unroll
            for (int k = 0; k < 4; k++) acc[i][j][k] = 0.0f;

    for (int k0 = 0; k0 < K; k0 += 32) {
        // synchronous tile load: 512 uint4 per plane
#pragma unroll
        for (int j = 0; j < 2; j++) {
            int idx = tid + j * 256;
            int r = idx >> 2, cc = idx & 3;
            size_t gA = offAB + (size_t)(m0 + r) * lda + k0 + cc * 8;
            size_t gB = offAB + (size_t)(n0 + r) * ldb + k0 + cc * 8;
            *(uint4*)(Ash + r * PITCH + cc * 8) = *(const uint4*)(Ah + gA);
            *(uint4*)(Asl + r * PITCH + cc * 8) = *(const uint4*)(Al + gA);
            *(uint4*)(Bsh + r * PITCH + cc * 8) = *(const uint4*)(Bth + gB);
            *(uint4*)(Bsl + r * PITCH + cc * 8) = *(const uint4*)(Btl + gB);
        }
        __syncthreads();

        const uint32_t* A32h = (const uint32_t*)Ash;
        const uint32_t* A32l = (const uint32_t*)Asl;
        const uint32_t* B32h = (const uint32_t*)Bsh;
        const uint32_t* B32l = (const uint32_t*)Bsl;

#pragma unroll
        for (int ks = 0; ks < 32; ks += 16) {
            uint32_t ah[4][4], al[4][4];
#pragma unroll
            for (int mt = 0; mt < 4; mt++) {
                int base = (wm0 + mt * 16 + lr) * (PITCH / 2) + (ks >> 1) + lc;
                ah[mt][0] = A32h[base];
                ah[mt][1] = A32h[base + 8 * (PITCH / 2)];
                ah[mt][2] = A32h[base + 4];
                ah[mt][3] = A32h[base + 8 * (PITCH / 2) + 4];
                al[mt][0] = A32l[base];
                al[mt][1] = A32l[base + 8 * (PITCH / 2)];
                al[mt][2] = A32l[base + 4];
                al[mt][3] = A32l[base + 8 * (PITCH / 2) + 4];
            }
#pragma unroll
            for (int nt = 0; nt < 4; nt++) {
                int bb = (wn0 + nt * 8 + lr) * (PITCH / 2) + (ks >> 1) + lc;
                uint32_t bh[2] = {B32h[bb], B32h[bb + 4]};
                uint32_t bl[2] = {B32l[bb], B32l[bb + 4]};
#pragma unroll
                for (int mt = 0; mt < 4; mt++) {
                    mma16(acc[mt][nt], ah[mt], bh);
                    mma16(acc[mt][nt], ah[mt], bl);
                    mma16(acc[mt][nt], al[mt], bh);
                }
            }
        }
        __syncthreads();
    }

    // epilogue
#pragma unroll
    for (int mt = 0; mt < 4; mt++)
#pragma unroll
        for (int nt = 0; nt < 4; nt++) {
            int r = m0 + wm0 + mt * 16 + lr;
            int c = n0 + wn0 + nt * 8 + 2 * lc;
            float b0 = bias ? bias[c] : 0.0f;
            float b1 = bias ? bias[c + 1] : 0.0f;
            float v00 = acc[mt][nt][0] * scale + b0;
            float v01 = acc[mt][nt][1] * scale + b1;
            float v10 = acc[mt][nt][2] * scale + b0;
            float v11 = acc[mt][nt][3] * scale + b1;
            if (OUT == 0) {
                float* C = outF + (size_t)z * cB;
                *(float2*)(C + (size_t)r * ldc + c) = make_float2(v00, v01);
                *(float2*)(C + (size_t)(r + 8) * ldc + c) = make_float2(v10, v11);
            } else if (OUT == 1) {
                bf16 h0, l0, h1, l1;
                split_bf(v00, h0, l0); split_bf(v01, h1, l1);
                *(uint32_t*)(outH + (size_t)r * ldc + c) = pk2(h0, h1);
                *(uint32_t*)(outL + (size_t)r * ldc + c) = pk2(l0, l1);
                split_bf(v10, h0, l0); split_bf(v11, h1, l1);
                *(uint32_t*)(outH + (size_t)(r + 8) * ldc + c) = pk2(h0, h1);
                *(uint32_t*)(outL + (size_t)(r + 8) * ldc + c) = pk2(l0, l1);
            } else {
                bf16 h, l;
                split_bf(v00, h, l);
                outH[(size_t)c * ldc + r] = h; outL[(size_t)c * ldc + r] = l;
                split_bf(v01, h, l);
                outH[(size_t)(c + 1) * ldc + r] = h; outL[(size_t)(c + 1) * ldc + r] = l;
                split_bf(v10, h, l);
                outH[(size_t)c * ldc + r + 8] = h; outL[(size_t)c * ldc + r + 8] = l;
                split_bf(v11, h, l);
                outH[(size_t)(c + 1) * ldc + r + 8] = h; outL[(size_t)(c + 1) * ldc + r + 8] = l;
            }
        }
}

// ---------------- softmax: probs -> attn (d_out) ----------------------------
#define SMROW 1032
__global__ __launch_bounds__(256) void softmax_kernel(
    const float* __restrict__ Sc, float* __restrict__ attn)
{
    extern __shared__ float ssc[];
    __shared__ float mF[32], iF[32], mB[32], iB[32];

    const int bh = blockIdx.y;
    const int q0 = blockIdx.x * 32;
    const int tid = threadIdx.x;

    const float* src = Sc + (size_t)bh * SS * SS + (size_t)q0 * SS;
    for (int i = tid; i < 32 * SS; i += 256) {
        int r = i >> 10, k = i & 1023;
        ssc[r * SMROW + k] = src[i];
    }
    __syncthreads();

    const int r = tid >> 3;
    const int t = tid & 7;
    const int q = q0 + r;
    const float* row = ssc + r * SMROW;

    float mf = -1e30f, mb = -1e30f;
#pragma unroll 8
    for (int i = 0; i < 128; i++) {
        int k = t + (i << 3);
        float v = row[k];
        if (k <= q) mf = fmaxf(mf, v);
        if (k >= q) mb = fmaxf(mb, v);
    }
#pragma unroll
    for (int o = 4; o > 0; o >>= 1) {
        mf = fmaxf(mf, __shfl_xor_sync(0xffffffffu, mf, o));
        mb = fmaxf(mb, __shfl_xor_sync(0xffffffffu, mb, o));
    }
    float sf = 0.0f, sb = 0.0f;
#pragma unroll 8
    for (int i = 0; i < 128; i++) {
        int k = t + (i << 3);
        float v = row[k];
        if (k <= q) sf += __expf(v - mf);
        if (k >= q) sb += __expf(v - mb);
    }
#pragma unroll
    for (int o = 4; o > 0; o >>= 1) {
        sf += __shfl_xor_sync(0xffffffffu, sf, o);
        sb += __shfl_xor_sync(0xffffffffu, sb, o);
    }
    if (t == 0) {
        mF[r] = mf; iF[r] = 1.0f / sf;
        mB[r] = mb; iB[r] = 1.0f / sb;
    }
    __syncthreads();

    float* dst = attn + (size_t)bh * SS * 2 * SS + (size_t)q0 * 2 * SS;
    for (int i = tid; i < 32 * SS; i += 256) {
        int rr = i >> 10, k = i & 1023;
        int qq = q0 + rr;
        float v = ssc[rr * SMROW + k];
        float pf = (k <= qq) ? __expf(v - mF[rr]) * iF[rr] : 0.0f;
        float pb = (k >= qq) ? __expf(v - mB[rr]) * iB[rr] : 0.0f;
        dst[(size_t)rr * 2048 + k] = pf;
        dst[(size_t)rr * 2048 + 1024 + k] = pb;
    }
}

// ---------------- PV: ctx = P @ V  (P split in-reg, V^T pre-split) ----------
__global__ __launch_bounds__(256) void pv_bf16(const float* __restrict__ attn)
{
    __shared__ __align__(16) bf16 Psh[128 * PITCH];
    __shared__ __align__(16) bf16 Psl[128 * PITCH];
    __shared__ __align__(16) bf16 Vsh[32 * PITCH];
    __shared__ __align__(16) bf16 Vsl[32 * PITCH];

    const int bh = blockIdx.z;
    const int dir = blockIdx.y;
    const int q0 = blockIdx.x * 128;
    const int b = bh >> 4, h = bh & 15;
    const int tid = threadIdx.x, lane = tid & 31, wid = tid >> 5;
    const int lr = lane >> 2, lc = lane & 3;

    const float* Pb = attn + (size_t)bh * SS * 2 * SS + (size_t)dir * SS;
    const bf16* Vth = g_VTh + (size_t)h * 32 * BS + (size_t)b * SS;
    const bf16* Vtl = g_VTl + (size_t)h * 32 * BS + (size_t)b * SS;

    float acc[4][4];
#pragma unroll
    for (int i = 0; i < 4; i++)
#pragma unroll
        for (int j = 0; j < 4; j++) acc[i][j] = 0.0f;

    for (int k0 = 0; k0 < SS; k0 += 32) {
        // P tile [128 q][32 k]: split fp32 -> bf16 hi/lo
#pragma unroll
        for (int j = 0; j < 2; j++) {
            int idx = tid + j * 256;
            int r = idx >> 2, cc = idx & 3;
            const float* src = Pb + (size_t)(q0 + r) * 2048 + k0 + cc * 8;
            float4 p0 = *(const float4*)(src);
            float4 p1 = *(const float4*)(src + 4);
            bf16 h0, l0, h1, l1, h2, l2, h3, l3, h4, l4, h5, l5, h6, l6, h7, l7;
            split_bf(p0.x, h0, l0); split_bf(p0.y, h1, l1);
            split_bf(p0.z, h2, l2); split_bf(p0.w, h3, l3);
            split_bf(p1.x, h4, l4); split_bf(p1.y, h5, l5);
            split_bf(p1.z, h6, l6); split_bf(p1.w, h7, l7);
            uint4 hv, lv;
            hv.x = pk2(h0, h1); hv.y = pk2(h2, h3);
            hv.z = pk2(h4, h5); hv.w = pk2(h6, h7);
            lv.x = pk2(l0, l1); lv.y = pk2(l2, l3);
            lv.z = pk2(l4, l5); lv.w = pk2(l6, l7);
            *(uint4*)(Psh + r * PITCH + cc * 8) = hv;
            *(uint4*)(Psl + r * PITCH + cc * 8) = lv;
        }
        // V tile [32 d][32 k]: one uint4 per thread
        {
            int half = tid >> 7;          // 0 hi, 1 lo
            int d = (tid >> 2) & 31;
            int cc = tid & 3;
            const bf16* src = (half == 0 ? Vth : Vtl);
            bf16* dst = (half == 0 ? Vsh : Vsl);
            *(uint4*)(dst + d * PITCH + cc * 8) =
                *(const uint4*)(src + (size_t)d * BS + k0 + cc * 8);
        }
        __syncthreads();

        const uint32_t* A32h = (const uint32_t*)Psh;
        const uint32_t* A32l = (const uint32_t*)Psl;
        const uint32_t* B32h = (const uint32_t*)Vsh;
        const uint32_t* B32l = (const uint32_t*)Vsl;

#pragma unroll
        for (int ks = 0; ks < 32; ks += 16) {
            int base = (wid * 16 + lr) * (PITCH / 2) + (ks >> 1) + lc;
            uint32_t ah[4] = {A32h[base], A32h[base + 8 * (PITCH / 2)],
                              A32h[base + 4], A32h[base + 8 * (PITCH / 2) + 4]};
            uint32_t al[4] = {A32l[base], A32l[base + 8 * (PITCH / 2)],
                              A32l[base + 4], A32l[base + 8 * (PITCH / 2) + 4]};
#pragma unroll
            for (int nt = 0; nt < 4; nt++) {
                int bb = (nt * 8 + lr) * (PITCH / 2) + (ks >> 1) + lc;
                uint32_t bh[2] = {B32h[bb], B32h[bb + 4]};
                uint32_t bl[2] = {B32l[bb], B32l[bb + 4]};
                mma16(acc[nt], ah, bh);
                mma16(acc[nt], ah, bl);
                mma16(acc[nt], al, bh);
            }
        }
        __syncthreads();
    }

    // epilogue: ctx split, col = dir*512 + h*32 + n
#pragma unroll
    for (int nt = 0; nt < 4; nt++) {
        int r = q0 + wid * 16 + lr;
        int c = dir * HDV + h * DV + nt * 8 + 2 * lc;
        bf16 h0, l0, h1, l1;
        split_bf(acc[nt][0], h0, l0); split_bf(acc[nt][1], h1, l1);
        *(uint32_t*)(g_Ch + (size_t)((size_t)b * SS + r) * DD + c) = pk2(h0, h1);
        *(uint32_t*)(g_Cl + (size_t)((size_t)b * SS + r) * DD + c) = pk2(l0, l1);
        split_bf(acc[nt][2], h0, l0); split_bf(acc[nt][3], h1, l1);
        *(uint32_t*)(g_Ch + (size_t)((size_t)b * SS + r + 8) * DD + c) = pk2(h0, h1);
        *(uint32_t*)(g_Cl + (size_t)((size_t)b * SS + r + 8) * DD + c) = pk2(l0, l1);
    }
}

// ---------------- launch -----------------------------------------------------
extern "C" void kernel_launch(void* const* d_in, const int* in_sizes, int n_in,
                              void* d_out, int out_size)
{
    const float* x  = (const float*)d_in[0];
    const float* Wq = (const float*)d_in[1];
    const float* bq = (const float*)d_in[2];
    const float* Wk = (const float*)d_in[3];
    const float* bk = (const float*)d_in[4];
    const float* Wv = (const float*)d_in[5];
    const float* bv = (const float*)d_in[6];
    const float* Wo = (const float*)d_in[7];
    const float* bo = (const float*)d_in[8];

    float* out  = (float*)d_out;
    float* attn = out + (size_t)BS * DD;

    bf16 *xh, *xl, *WqTh, *WqTl, *WkTh, *WkTl, *WvTh, *WvTl, *WoTh, *WoTl;
    bf16 *Qh, *Ql, *Kh, *Kl, *VTh, *VTl, *Ch, *Cl;
    float* pS;
    cudaGetSymbolAddress((void**)&xh, g_xh);     cudaGetSymbolAddress((void**)&xl, g_xl);
    cudaGetSymbolAddress((void**)&WqTh, g_WqTh); cudaGetSymbolAddress((void**)&WqTl, g_WqTl);
    cudaGetSymbolAddress((void**)&WkTh, g_WkTh); cudaGetSymbolAddress((void**)&WkTl, g_WkTl);
    cudaGetSymbolAddress((void**)&WvTh, g_WvTh); cudaGetSymbolAddress((void**)&WvTl, g_WvTl);
    cudaGetSymbolAddress((void**)&WoTh, g_WoTh); cudaGetSymbolAddress((void**)&WoTl, g_WoTl);
    cudaGetSymbolAddress((void**)&Qh, g_Qh);     cudaGetSymbolAddress((void**)&Ql, g_Ql);
    cudaGetSymbolAddress((void**)&Kh, g_Kh);     cudaGetSymbolAddress((void**)&Kl, g_Kl);
    cudaGetSymbolAddress((void**)&VTh, g_VTh);   cudaGetSymbolAddress((void**)&VTl, g_VTl);
    cudaGetSymbolAddress((void**)&Ch, g_Ch);     cudaGetSymbolAddress((void**)&Cl, g_Cl);
    cudaGetSymbolAddress((void**)&pS, g_S);

    cudaFuncSetAttribute(softmax_kernel,
                         cudaFuncAttributeMaxDynamicSharedMemorySize, 32 * SMROW * 4);

    // split passes
    split_x_kernel<<<512, 256>>>(x, xh, xl, BS * DD / 4);
    splitT_kernel<<<dim3(32, 32), dim3(32, 8)>>>(Wq, WqTh, WqTl, DD, HDQ);
    splitT_kernel<<<dim3(32, 32), dim3(32, 8)>>>(Wk, WkTh, WkTl, DD, HDQ);
    splitT_kernel<<<dim3(16, 32), dim3(32, 8)>>>(Wv, WvTh, WvTl, DD, HDV);
    splitT_kernel<<<dim3(32, 32), dim3(32, 8)>>>(Wo, WoTh, WoTl, DD, DD);

    // projections
    gemm_bf16<1><<<dim3(8, 32, 1), 256>>>(
        xh, xl, DD, WqTh, WqTl, DD, bq, 1.0f,
        nullptr, Qh, Ql, HDQ, BS, HDQ, DD, 0, 0, 0);
    gemm_bf16<1><<<dim3(8, 32, 1), 256>>>(
        xh, xl, DD, WkTh, WkTl, DD, bk, 1.0f,
        nullptr, Kh, Kl, HDQ, BS, HDQ, DD, 0, 0, 0);
    gemm_bf16<2><<<dim3(4, 32, 1), 256>>>(
        xh, xl, DD, WvTh, WvTl, DD, bv, 1.0f,
        nullptr, VTh, VTl, BS, BS, HDV, DD, 0, 0, 0);

    // scores: per (b,h): Q slice @ K slice^T * 0.125
    gemm_bf16<0><<<dim3(8, 8, BB * HH), 256>>>(
        Qh, Ql, HDQ, Kh, Kl, HDQ, nullptr, 0.125f,
        pS, nullptr, nullptr, SS, SS, SS, DQ,
        (size_t)SS * HDQ, (size_t)DQ, (size_t)SS * SS);

    // softmax + prob write
    softmax_kernel<<<dim3(SS / 32, BB * HH), 256, 32 * SMROW * 4>>>(pS, attn);

    // PV
    pv_bf16<<<dim3(SS / 128, 2, BB * HH), 256>>>(attn);

    // output projection
    gemm_bf16<0><<<dim3(8, 32, 1), 256>>>(
        Ch, Cl, DD, WoTh, WoTl, DD, bo, 1.0f,
        out, nullptr, nullptr, DD, BS, DD, DD, 0, 0, 0);
}

// round 7
// speedup vs baseline: 1.6383x; 1.0476x over previous
#include <cuda_runtime.h>
#include <cuda_bf16.h>
#include <math.h>
#include <stdint.h>

#define BB 4
#define SS 1024
#define DD 1024
#define HH 16
#define DQ 64
#define DV 32
#define BS (BB*SS)          // 4096
#define HDQ (HH*DQ)         // 1024
#define HDV (HH*DV)         // 512

typedef __nv_bfloat16 bf16;

// ---------------- scratch (device globals; allocation-free rule) ------------
__device__ bf16 g_xh[BS * DD],  g_xl[BS * DD];            // split input
__device__ bf16 g_WqTh[HDQ * DD], g_WqTl[HDQ * DD];       // W^T split [N][K]
__device__ bf16 g_WkTh[HDQ * DD], g_WkTl[HDQ * DD];
__device__ bf16 g_WvTh[HDV * DD], g_WvTl[HDV * DD];
__device__ bf16 g_WoTh[DD * DD],  g_WoTl[DD * DD];
__device__ bf16 g_Qh[BS * HDQ],  g_Ql[BS * HDQ];          // [token][d]
__device__ bf16 g_Kh[BS * HDQ],  g_Kl[BS * HDQ];          // [token][d]
__device__ bf16 g_VTh[HDV * BS], g_VTl[HDV * BS];         // V^T [d][token]
__device__ bf16 g_Ch[BS * DD],   g_Cl[BS * DD];           // ctx split
__device__ float g_S[(size_t)BB * HH * SS * SS];          // scores fp32

// ---------------- helpers ---------------------------------------------------
__device__ __forceinline__ void split_bf(float f, bf16& h, bf16& l) {
    h = __float2bfloat16(f);
    l = __float2bfloat16(f - __bfloat162float(h));
}
__device__ __forceinline__ uint32_t pk2(bf16 a, bf16 b) {
    return (uint32_t)__bfloat16_as_ushort(a) |
           ((uint32_t)__bfloat16_as_ushort(b) << 16);
}
__device__ __forceinline__ void mma16(float* c, const uint32_t* a, const uint32_t* b) {
    asm("mma.sync.aligned.m16n8k16.row.col.f32.bf16.bf16.f32 "
        "{%0,%1,%2,%3}, {%4,%5,%6,%7}, {%8,%9}, {%0,%1,%2,%3};"
        : "+f"(c[0]), "+f"(c[1]), "+f"(c[2]), "+f"(c[3])
        : "r"(a[0]), "r"(a[1]), "r"(a[2]), "r"(a[3]), "r"(b[0]), "r"(b[1]));
}
__device__ __forceinline__ void cpa16(uint32_t s, const void* g) {
    asm volatile("cp.async.cg.shared.global [%0], [%1], 16;" :: "r"(s), "l"(g));
}
__device__ __forceinline__ void cp_commit() {
    asm volatile("cp.async.commit_group;");
}
__device__ __forceinline__ void cp_wait1() {
    asm volatile("cp.async.wait_group 1;");
}
__device__ __forceinline__ void cp_wait0() {
    asm volatile("cp.async.wait_group 0;");
}

// ---------------- split pre-passes ------------------------------------------
__global__ __launch_bounds__(256) void split_x_kernel(
    const float* __restrict__ in, bf16* __restrict__ hi,
    bf16* __restrict__ lo, int n4)
{
    for (int i = blockIdx.x * 256 + threadIdx.x; i < n4; i += gridDim.x * 256) {
        float4 v = ((const float4*)in)[i];
        bf16 h0, l0, h1, l1, h2, l2, h3, l3;
        split_bf(v.x, h0, l0); split_bf(v.y, h1, l1);
        split_bf(v.z, h2, l2); split_bf(v.w, h3, l3);
        ((uint2*)hi)[i] = make_uint2(pk2(h0, h1), pk2(h2, h3));
        ((uint2*)lo)[i] = make_uint2(pk2(l0, l1), pk2(l2, l3));
    }
}

// Transpose + split: W [K][N] fp32 -> T [N][K] bf16 hi/lo
__global__ void splitT_kernel(const float* __restrict__ W,
                              bf16* __restrict__ Th, bf16* __restrict__ Tl,
                              int K, int N)
{
    __shared__ float t[32][33];
    const int n0 = blockIdx.x * 32, k0 = blockIdx.y * 32;
    const int tx = threadIdx.x, ty = threadIdx.y;
#pragma unroll
    for (int i = 0; i < 32; i += 8)
        t[ty + i][tx] = W[(size_t)(k0 + ty + i) * N + n0 + tx];
    __syncthreads();
#pragma unroll
    for (int i = 0; i < 32; i += 8) {
        float v = t[tx][ty + i];
        bf16 h, l; split_bf(v, h, l);
        Th[(size_t)(n0 + ty + i) * K + k0 + tx] = h;
        Tl[(size_t)(n0 + ty + i) * K + k0 + tx] = l;
    }
}

// ---------------- unified bf16-split GEMM (cp.async double-buffered) --------
// C[M,N] = (A @ Bt^T) * scale + bias   (A row-major [M][K], Bt row-major [N][K])
// OUT=0: fp32 C. OUT=1: split bf16 row-major. OUT=2: split bf16 transposed.
// 128x128 tile, BK=32, 8 warps (2x4 warp grid), warp tile 64x32.
#define PITCH 40             // bf16 per smem row (32 data + 8 pad)
#define TSZ (128 * PITCH)    // one plane-buffer, bf16 elements
// smem slot map: plane 0=Ah 1=Al 2=Bh 3=Bl; element offset = (plane*2+buf)*TSZ
#define GEMM_SMEM (8 * TSZ * 2)   // 81920 B

__device__ __forceinline__ int slot_off(int plane, int buf) {
    return (plane * 2 + buf) * TSZ;
}

template<int OUT>
__global__ __launch_bounds__(256) void gemm_bf16(
    const bf16* __restrict__ Ah, const bf16* __restrict__ Al, int lda,
    const bf16* __restrict__ Bth, const bf16* __restrict__ Btl, int ldb,
    const float* __restrict__ bias, float scale,
    float* __restrict__ outF, bf16* __restrict__ outH, bf16* __restrict__ outL,
    int ldc, int M, int N, int K, size_t zb, size_t zh, size_t cB)
{
    extern __shared__ __align__(16) bf16 smem[];

    const int z = blockIdx.z;
    const size_t offAB = (size_t)(z >> 4) * zb + (size_t)(z & 15) * zh;

    const int m0 = blockIdx.y * 128, n0 = blockIdx.x * 128;
    const int tid = threadIdx.x, lane = tid & 31, wid = tid >> 5;
    const int wm0 = (wid >> 2) * 64, wn0 = (wid & 3) * 32;
    const int lr = lane >> 2, lc = lane & 3;

    const uint32_t sbase = (uint32_t)__cvta_generic_to_shared(smem);

    float acc[4][4][4];
#pragma unroll
    for (int i = 0; i < 4; i++)
#pragma unroll
        for (int j = 0; j < 4; j++)
#pragma unroll
            for (int k = 0; k < 4; k++) acc[i][j][k] = 0.0f;

    const int nk = K / 32;

    auto loadAB = [&](int buf, int k0) {
#pragma unroll
        for (int j = 0; j < 2; j++) {
            int idx = tid + j * 256;
            int r = idx >> 2, cc = idx & 3;
            int rp = r * PITCH + cc * 8;
            size_t gA = offAB + (size_t)(m0 + r) * lda + k0 + cc * 8;
            size_t gB = offAB + (size_t)(n0 + r) * ldb + k0 + cc * 8;
            cpa16(sbase + (slot_off(0, buf) + rp) * 2, Ah + gA);
            cpa16(sbase + (slot_off(1, buf) + rp) * 2, Al + gA);
            cpa16(sbase + (slot_off(2, buf) + rp) * 2, Bth + gB);
            cpa16(sbase + (slot_off(3, buf) + rp) * 2, Btl + gB);
        }
    };

    loadAB(0, 0);
    cp_commit();

    for (int kt = 0; kt < nk; kt++) {
        const int buf = kt & 1;
        if (kt + 1 < nk) {
            loadAB(buf ^ 1, (kt + 1) * 32);
            cp_commit();
            cp_wait1();
        } else {
            cp_wait0();
        }
        __syncthreads();

        const uint32_t* A32h = (const uint32_t*)(smem + slot_off(0, buf));
        const uint32_t* A32l = (const uint32_t*)(smem + slot_off(1, buf));
        const uint32_t* B32h = (const uint32_t*)(smem + slot_off(2, buf));
        const uint32_t* B32l = (const uint32_t*)(smem + slot_off(3, buf));

#pragma unroll
        for (int ks = 0; ks < 32; ks += 16) {
            uint32_t ah[4][4], al[4][4];
#pragma unroll
            for (int mt = 0; mt < 4; mt++) {
                int base = (wm0 + mt * 16 + lr) * (PITCH / 2) + (ks >> 1) + lc;
                ah[mt][0] = A32h[base];
                ah[mt][1] = A32h[base + 8 * (PITCH / 2)];
                ah[mt][2] = A32h[base + 4];
                ah[mt][3] = A32h[base + 8 * (PITCH / 2) + 4];
                al[mt][0] = A32l[base];
                al[mt][1] = A32l[base + 8 * (PITCH / 2)];
                al[mt][2] = A32l[base + 4];
                al[mt][3] = A32l[base + 8 * (PITCH / 2) + 4];
            }
#pragma unroll
            for (int nt = 0; nt < 4; nt++) {
                int bb = (wn0 + nt * 8 + lr) * (PITCH / 2) + (ks >> 1) + lc;
                uint32_t bh[2] = {B32h[bb], B32h[bb + 4]};
                uint32_t bl[2] = {B32l[bb], B32l[bb + 4]};
#pragma unroll
                for (int mt = 0; mt < 4; mt++) {
                    mma16(acc[mt][nt], ah[mt], bh);
                    mma16(acc[mt][nt], ah[mt], bl);
                    mma16(acc[mt][nt], al[mt], bh);
                }
            }
        }
        __syncthreads();
    }

    // epilogue
#pragma unroll
    for (int mt = 0; mt < 4; mt++)
#pragma unroll
        for (int nt = 0; nt < 4; nt++) {
            int r = m0 + wm0 + mt * 16 + lr;
            int c = n0 + wn0 + nt * 8 + 2 * lc;
            float b0 = bias ? bias[c] : 0.0f;
            float b1 = bias ? bias[c + 1] : 0.0f;
            float v00 = acc[mt][nt][0] * scale + b0;
            float v01 = acc[mt][nt][1] * scale + b1;
            float v10 = acc[mt][nt][2] * scale + b0;
            float v11 = acc[mt][nt][3] * scale + b1;
            if (OUT == 0) {
                float* C = outF + (size_t)z * cB;
                *(float2*)(C + (size_t)r * ldc + c) = make_float2(v00, v01);
                *(float2*)(C + (size_t)(r + 8) * ldc + c) = make_float2(v10, v11);
            } else if (OUT == 1) {
                bf16 h0, l0, h1, l1;
                split_bf(v00, h0, l0); split_bf(v01, h1, l1);
                *(uint32_t*)(outH + (size_t)r * ldc + c) = pk2(h0, h1);
                *(uint32_t*)(outL + (size_t)r * ldc + c) = pk2(l0, l1);
                split_bf(v10, h0, l0); split_bf(v11, h1, l1);
                *(uint32_t*)(outH + (size_t)(r + 8) * ldc + c) = pk2(h0, h1);
                *(uint32_t*)(outL + (size_t)(r + 8) * ldc + c) = pk2(l0, l1);
            } else {
                bf16 h, l;
                split_bf(v00, h, l);
                outH[(size_t)c * ldc + r] = h; outL[(size_t)c * ldc + r] = l;
                split_bf(v01, h, l);
                outH[(size_t)(c + 1) * ldc + r] = h; outL[(size_t)(c + 1) * ldc + r] = l;
                split_bf(v10, h, l);
                outH[(size_t)c * ldc + r + 8] = h; outL[(size_t)c * ldc + r + 8] = l;
                split_bf(v11, h, l);
                outH[(size_t)(c + 1) * ldc + r + 8] = h; outL[(size_t)(c + 1) * ldc + r + 8] = l;
            }
        }
}

// ---------------- softmax: probs -> attn (d_out) ----------------------------
#define SMROW 1032
__global__ __launch_bounds__(256) void softmax_kernel(
    const float* __restrict__ Sc, float* __restrict__ attn)
{
    extern __shared__ float ssc[];
    __shared__ float mF[32], iF[32], mB[32], iB[32];

    const int bh = blockIdx.y;
    const int q0 = blockIdx.x * 32;
    const int tid = threadIdx.x;

    const float* src = Sc + (size_t)bh * SS * SS + (size_t)q0 * SS;
    for (int i = tid; i < 32 * SS; i += 256) {
        int r = i >> 10, k = i & 1023;
        ssc[r * SMROW + k] = src[i];
    }
    __syncthreads();

    const int r = tid >> 3;
    const int t = tid & 7;
    const int q = q0 + r;
    const float* row = ssc + r * SMROW;

    float mf = -1e30f, mb = -1e30f;
#pragma unroll 8
    for (int i = 0; i < 128; i++) {
        int k = t + (i << 3);
        float v = row[k];
        if (k <= q) mf = fmaxf(mf, v);
        if (k >= q) mb = fmaxf(mb, v);
    }
#pragma unroll
    for (int o = 4; o > 0; o >>= 1) {
        mf = fmaxf(mf, __shfl_xor_sync(0xffffffffu, mf, o));
        mb = fmaxf(mb, __shfl_xor_sync(0xffffffffu, mb, o));
    }
    float sf = 0.0f, sb = 0.0f;
#pragma unroll 8
    for (int i = 0; i < 128; i++) {
        int k = t + (i << 3);
        float v = row[k];
        if (k <= q) sf += __expf(v - mf);
        if (k >= q) sb += __expf(v - mb);
    }
#pragma unroll
    for (int o = 4; o > 0; o >>= 1) {
        sf += __shfl_xor_sync(0xffffffffu, sf, o);
        sb += __shfl_xor_sync(0xffffffffu, sb, o);
    }
    if (t == 0) {
        mF[r] = mf; iF[r] = 1.0f / sf;
        mB[r] = mb; iB[r] = 1.0f / sb;
    }
    __syncthreads();

    float* dst = attn + (size_t)bh * SS * 2 * SS + (size_t)q0 * 2 * SS;
    for (int i = tid; i < 32 * SS; i += 256) {
        int rr = i >> 10, k = i & 1023;
        int qq = q0 + rr;
        float v = ssc[rr * SMROW + k];
        float pf = (k <= qq) ? __expf(v - mF[rr]) * iF[rr] : 0.0f;
        float pb = (k >= qq) ? __expf(v - mB[rr]) * iB[rr] : 0.0f;
        dst[(size_t)rr * 2048 + k] = pf;
        dst[(size_t)rr * 2048 + 1024 + k] = pb;
    }
}

// ---------------- PV: ctx = P @ V  (P split in-reg, V^T cp.async) -----------
// smem: P_hi[buf] planes 0..1, P_lo 2..3 (TSZ each); V planes after 4*TSZ,
// (vplane*2+buf)*VSZ with VSZ = 32*PITCH.
#define VSZ (32 * PITCH)
#define PV_SMEM ((4 * TSZ + 4 * VSZ) * 2)   // 51200 B

__global__ __launch_bounds__(256) void pv_bf16(const float* __restrict__ attn)
{
    extern __shared__ __align__(16) bf16 smem[];

    const int bh = blockIdx.z;
    const int dir = blockIdx.y;
    const int q0 = blockIdx.x * 128;
    const int b = bh >> 4, h = bh & 15;
    const int tid = threadIdx.x, lane = tid & 31, wid = tid >> 5;
    const int lr = lane >> 2, lc = lane & 3;

    const float* Pb = attn + (size_t)bh * SS * 2 * SS + (size_t)dir * SS;
    const bf16* Vth = g_VTh + (size_t)h * 32 * BS + (size_t)b * SS;
    const bf16* Vtl = g_VTl + (size_t)h * 32 * BS + (size_t)b * SS;

    const uint32_t sbase = (uint32_t)__cvta_generic_to_shared(smem);

    float acc[4][4];
#pragma unroll
    for (int i = 0; i < 4; i++)
#pragma unroll
        for (int j = 0; j < 4; j++) acc[i][j] = 0.0f;

    auto loadP = [&](int buf, int k0) {
#pragma unroll
        for (int j = 0; j < 2; j++) {
            int idx = tid + j * 256;
            int r = idx >> 2, cc = idx & 3;
            const float* src = Pb + (size_t)(q0 + r) * 2048 + k0 + cc * 8;
            float4 p0 = *(const float4*)(src);
            float4 p1 = *(const float4*)(src + 4);
            bf16 h0, l0, h1, l1, h2, l2, h3, l3, h4, l4, h5, l5, h6, l6, h7, l7;
            split_bf(p0.x, h0, l0); split_bf(p0.y, h1, l1);
            split_bf(p0.z, h2, l2); split_bf(p0.w, h3, l3);
            split_bf(p1.x, h4, l4); split_bf(p1.y, h5, l5);
            split_bf(p1.z, h6, l6); split_bf(p1.w, h7, l7);
            uint4 hv = make_uint4(pk2(h0, h1), pk2(h2, h3), pk2(h4, h5), pk2(h6, h7));
            uint4 lv = make_uint4(pk2(l0, l1), pk2(l2, l3), pk2(l4, l5), pk2(l6, l7));
            *(uint4*)(smem + (0 * 2 + buf) * TSZ + r * PITCH + cc * 8) = hv;
            *(uint4*)(smem + (1 * 2 + buf) * TSZ + r * PITCH + cc * 8) = lv;
        }
    };
    auto loadV = [&](int buf, int k0) {
        int half = tid >> 7;          // 0 hi, 1 lo
        int d = (tid >> 2) & 31;
        int cc = tid & 3;
        const bf16* src = (half == 0 ? Vth : Vtl);
        uint32_t s = sbase + (4 * TSZ + (half * 2 + buf) * VSZ
                              + d * PITCH + cc * 8) * 2;
        cpa16(s, src + (size_t)d * BS + k0 + cc * 8);
    };

    loadV(0, 0);
    cp_commit();
    loadP(0, 0);

    const int nk = SS / 32;
    for (int kt = 0; kt < nk; kt++) {
        const int buf = kt & 1;
        if (kt + 1 < nk) {
            loadV(buf ^ 1, (kt + 1) * 32);
            cp_commit();
            cp_wait1();
        } else {
            cp_wait0();
        }
        __syncthreads();
        if (kt + 1 < nk) loadP(buf ^ 1, (kt + 1) * 32);

        const uint32_t* A32h = (const uint32_t*)(smem + (0 * 2 + buf) * TSZ);
        const uint32_t* A32l = (const uint32_t*)(smem + (1 * 2 + buf) * TSZ);
        const uint32_t* B32h = (const uint32_t*)(smem + 4 * TSZ + (0 * 2 + buf) * VSZ);
        const uint32_t* B32l = (const uint32_t*)(smem + 4 * TSZ + (1 * 2 + buf) * VSZ);

#pragma unroll
        for (int ks = 0; ks < 32; ks += 16) {
            int base = (wid * 16 + lr) * (PITCH / 2) + (ks >> 1) + lc;
            uint32_t ah[4] = {A32h[base], A32h[base + 8 * (PITCH / 2)],
                              A32h[base + 4], A32h[base + 8 * (PITCH / 2) + 4]};
            uint32_t al[4] = {A32l[base], A32l[base + 8 * (PITCH / 2)],
                              A32l[base + 4], A32l[base + 8 * (PITCH / 2) + 4]};
#pragma unroll
            for (int nt = 0; nt < 4; nt++) {
                int bb = (nt * 8 + lr) * (PITCH / 2) + (ks >> 1) + lc;
                uint32_t bh[2] = {B32h[bb], B32h[bb + 4]};
                uint32_t bl[2] = {B32l[bb], B32l[bb + 4]};
                mma16(acc[nt], ah, bh);
                mma16(acc[nt], ah, bl);
                mma16(acc[nt], al, bh);
            }
        }
        __syncthreads();
    }

    // epilogue: ctx split, col = dir*512 + h*32 + n
#pragma unroll
    for (int nt = 0; nt < 4; nt++) {
        int r = q0 + wid * 16 + lr;
        int c = dir * HDV + h * DV + nt * 8 + 2 * lc;
        bf16 h0, l0, h1, l1;
        split_bf(acc[nt][0], h0, l0); split_bf(acc[nt][1], h1, l1);
        *(uint32_t*)(g_Ch + (size_t)((size_t)b * SS + r) * DD + c) = pk2(h0, h1);
        *(uint32_t*)(g_Cl + (size_t)((size_t)b * SS + r) * DD + c) = pk2(l0, l1);
        split_bf(acc[nt][2], h0, l0); split_bf(acc[nt][3], h1, l1);
        *(uint32_t*)(g_Ch + (size_t)((size_t)b * SS + r + 8) * DD + c) = pk2(h0, h1);
        *(uint32_t*)(g_Cl + (size_t)((size_t)b * SS + r + 8) * DD + c) = pk2(l0, l1);
    }
}

// ---------------- launch -----------------------------------------------------
extern "C" void kernel_launch(void* const* d_in, const int* in_sizes, int n_in,
                              void* d_out, int out_size)
{
    const float* x  = (const float*)d_in[0];
    const float* Wq = (const float*)d_in[1];
    const float* bq = (const float*)d_in[2];
    const float* Wk = (const float*)d_in[3];
    const float* bk = (const float*)d_in[4];
    const float* Wv = (const float*)d_in[5];
    const float* bv = (const float*)d_in[6];
    const float* Wo = (const float*)d_in[7];
    const float* bo = (const float*)d_in[8];

    float* out  = (float*)d_out;
    float* attn = out + (size_t)BS * DD;

    bf16 *xh, *xl, *WqTh, *WqTl, *WkTh, *WkTl, *WvTh, *WvTl, *WoTh, *WoTl;
    bf16 *Qh, *Ql, *Kh, *Kl, *VTh, *VTl, *Ch, *Cl;
    float* pS;
    cudaGetSymbolAddress((void**)&xh, g_xh);     cudaGetSymbolAddress((void**)&xl, g_xl);
    cudaGetSymbolAddress((void**)&WqTh, g_WqTh); cudaGetSymbolAddress((void**)&WqTl, g_WqTl);
    cudaGetSymbolAddress((void**)&WkTh, g_WkTh); cudaGetSymbolAddress((void**)&WkTl, g_WkTl);
    cudaGetSymbolAddress((void**)&WvTh, g_WvTh); cudaGetSymbolAddress((void**)&WvTl, g_WvTl);
    cudaGetSymbolAddress((void**)&WoTh, g_WoTh); cudaGetSymbolAddress((void**)&WoTl, g_WoTl);
    cudaGetSymbolAddress((void**)&Qh, g_Qh);     cudaGetSymbolAddress((void**)&Ql, g_Ql);
    cudaGetSymbolAddress((void**)&Kh, g_Kh);     cudaGetSymbolAddress((void**)&Kl, g_Kl);
    cudaGetSymbolAddress((void**)&VTh, g_VTh);   cudaGetSymbolAddress((void**)&VTl, g_VTl);
    cudaGetSymbolAddress((void**)&Ch, g_Ch);     cudaGetSymbolAddress((void**)&Cl, g_Cl);
    cudaGetSymbolAddress((void**)&pS, g_S);

    cudaFuncSetAttribute(gemm_bf16<0>, cudaFuncAttributeMaxDynamicSharedMemorySize, GEMM_SMEM);
    cudaFuncSetAttribute(gemm_bf16<1>, cudaFuncAttributeMaxDynamicSharedMemorySize, GEMM_SMEM);
    cudaFuncSetAttribute(gemm_bf16<2>, cudaFuncAttributeMaxDynamicSharedMemorySize, GEMM_SMEM);
    cudaFuncSetAttribute(pv_bf16, cudaFuncAttributeMaxDynamicSharedMemorySize, PV_SMEM);
    cudaFuncSetAttribute(softmax_kernel,
                         cudaFuncAttributeMaxDynamicSharedMemorySize, 32 * SMROW * 4);

    // split passes
    split_x_kernel<<<512, 256>>>(x, xh, xl, BS * DD / 4);
    splitT_kernel<<<dim3(32, 32), dim3(32, 8)>>>(Wq, WqTh, WqTl, DD, HDQ);
    splitT_kernel<<<dim3(32, 32), dim3(32, 8)>>>(Wk, WkTh, WkTl, DD, HDQ);
    splitT_kernel<<<dim3(16, 32), dim3(32, 8)>>>(Wv, WvTh, WvTl, DD, HDV);
    splitT_kernel<<<dim3(32, 32), dim3(32, 8)>>>(Wo, WoTh, WoTl, DD, DD);

    // projections
    gemm_bf16<1><<<dim3(8, 32, 1), 256, GEMM_SMEM>>>(
        xh, xl, DD, WqTh, WqTl, DD, bq, 1.0f,
        nullptr, Qh, Ql, HDQ, BS, HDQ, DD, 0, 0, 0);
    gemm_bf16<1><<<dim3(8, 32, 1), 256, GEMM_SMEM>>>(
        xh, xl, DD, WkTh, WkTl, DD, bk, 1.0f,
        nullptr, Kh, Kl, HDQ, BS, HDQ, DD, 0, 0, 0);
    gemm_bf16<2><<<dim3(4, 32, 1), 256, GEMM_SMEM>>>(
        xh, xl, DD, WvTh, WvTl, DD, bv, 1.0f,
        nullptr, VTh, VTl, BS, BS, HDV, DD, 0, 0, 0);

    // scores: per (b,h): Q slice @ K slice^T * 0.125
    gemm_bf16<0><<<dim3(8, 8, BB * HH), 256, GEMM_SMEM>>>(
        Qh, Ql, HDQ, Kh, Kl, HDQ, nullptr, 0.125f,
        pS, nullptr, nullptr, SS, SS, SS, DQ,
        (size_t)SS * HDQ, (size_t)DQ, (size_t)SS * SS);

    // softmax + prob write
    softmax_kernel<<<dim3(SS / 32, BB * HH), 256, 32 * SMROW * 4>>>(pS, attn);

    // PV
    pv_bf16<<<dim3(SS / 128, 2, BB * HH), 256, PV_SMEM>>>(attn);

    // output projection
    gemm_bf16<0><<<dim3(8, 32, 1), 256, GEMM_SMEM>>>(
        Ch, Cl, DD, WoTh, WoTl, DD, bo, 1.0f,
        out, nullptr, nullptr, DD, BS, DD, DD, 0, 0, 0);
}